// round 4
// baseline (speedup 1.0000x reference)
#include <cuda_runtime.h>
#include <cuda_bf16.h>
#include <math.h>

// ---------------- problem constants ----------------
#define Bc   4
#define Sc   256
#define SKc  512
#define Dc   1024
#define NHc  16
#define NKVc 4
#define HDc  64
#define KVDc (NKVc*HDc)   // 256
#define DEc  4096
#define NEc  8
#define LN_EPS 1e-5f
#define QSCALE 0.125f     // HD^-0.5

// ---------------- scratch (device globals; no allocs allowed) ----------------
__device__ float g_ln  [Bc*Sc*Dc];                       // 4 MB  (reused for ln1/ln2/ln3)
__device__ float g_q   [Bc*Sc*Dc];                       // 4 MB
__device__ float g_k   [Bc*SKc*KVDc];                    // 2 MB  (self uses first B*S rows)
__device__ float g_v   [Bc*SKc*KVDc];                    // 2 MB
__device__ float g_sc  [(size_t)Bc*NHc*Sc*SKc];          // 32 MB (scores, max Skv=512)
__device__ float g_ctx [Bc*Sc*Dc];                       // 4 MB
__device__ float g_res [Bc*Sc*Dc];                       // 4 MB  (running hidden)
__device__ float g_t1  [(size_t)NEc*Bc*Sc*DEc];          // 128 MB (x@w1, then h)
__device__ float g_t3  [(size_t)NEc*Bc*Sc*DEc];          // 128 MB (x@w3)
__device__ float g_pout[(size_t)NEc*Bc*Sc*Dc];           // 32 MB (per-pair expert out)
__device__ float g_coef[NEc*Bc];

// ---------------- routing ----------------
__global__ void k_route(const int* __restrict__ langs) {
    if (threadIdx.x == 0 && blockIdx.x == 0) {
        for (int b = 0; b < Bc; b++) {
            int l0 = langs[2*b], l1 = langs[2*b+1];
            int cnt = (l0 > 3) + (l1 > 3);
            float rw = (cnt == 0) ? 1.f : 1.f / (float)cnt;
            for (int e = 0; e < NEc; e++) {
                int code = 4 + e;
                g_coef[e*Bc + b] = ((l0 == code) || (l1 == code)) ? rw : 0.f;
            }
        }
    }
}

// ---------------- layernorm (block per row) ----------------
__global__ void k_ln(const float* __restrict__ x, const float* __restrict__ g,
                     const float* __restrict__ bta, float* __restrict__ y) {
    int row = blockIdx.x;
    int tid = threadIdx.x;
    const float* xr = x + (size_t)row * Dc;
    float s = 0.f, s2 = 0.f;
    for (int i = tid; i < Dc; i += 256) { float v = xr[i]; s += v; s2 += v*v; }
    __shared__ float r1[256], r2[256];
    r1[tid] = s; r2[tid] = s2; __syncthreads();
    for (int off = 128; off > 0; off >>= 1) {
        if (tid < off) { r1[tid] += r1[tid+off]; r2[tid] += r2[tid+off]; }
        __syncthreads();
    }
    float mean = r1[0] * (1.f/Dc);
    float var  = r2[0] * (1.f/Dc) - mean*mean;
    float inv  = rsqrtf(var + LN_EPS);
    for (int i = tid; i < Dc; i += 256)
        y[(size_t)row*Dc + i] = (xr[i] - mean) * inv * g[i] + bta[i];
}

// ---------------- generic 128x128x8 SGEMM body ----------------
// mode: 0 = plain, 1 = +bias, 2 = (+bias)*scale, 3 = +bias+res
__device__ __forceinline__ void sgemm_tile(
    const float* __restrict__ A, const float* __restrict__ Bm, float* __restrict__ C,
    int M, int N, int K,
    const float* __restrict__ bias, const float* __restrict__ res,
    float scale, int mode)
{
    __shared__ float As[8][128];
    __shared__ float Bs[8][128];
    int tid = threadIdx.x;
    int bm = blockIdx.y * 128;
    int bn = blockIdx.x * 128;
    int tx = tid & 15, ty = tid >> 4;

    float acc[8][8];
    #pragma unroll
    for (int i = 0; i < 8; i++)
        #pragma unroll
        for (int j = 0; j < 8; j++) acc[i][j] = 0.f;

    int aRow = tid >> 1;             // 0..127
    int aCol = (tid & 1) * 4;        // 0 or 4
    int bRow = tid >> 5;             // 0..7
    int bCol = (tid & 31) * 4;       // 0..124

    const float* Ag = A  + (size_t)(bm + aRow) * K + aCol;
    const float* Bg = Bm + (size_t)bRow * N + bn + bCol;

    for (int k0 = 0; k0 < K; k0 += 8) {
        float4 a4 = *reinterpret_cast<const float4*>(Ag + k0);
        As[aCol+0][aRow] = a4.x;
        As[aCol+1][aRow] = a4.y;
        As[aCol+2][aRow] = a4.z;
        As[aCol+3][aRow] = a4.w;
        float4 b4 = *reinterpret_cast<const float4*>(Bg + (size_t)k0 * N);
        *reinterpret_cast<float4*>(&Bs[bRow][bCol]) = b4;
        __syncthreads();
        #pragma unroll
        for (int kk = 0; kk < 8; kk++) {
            float ra[8], rb[8];
            #pragma unroll
            for (int i = 0; i < 8; i++) ra[i] = As[kk][ty*8 + i];
            #pragma unroll
            for (int j = 0; j < 8; j++) rb[j] = Bs[kk][tx*8 + j];
            #pragma unroll
            for (int i = 0; i < 8; i++)
                #pragma unroll
                for (int j = 0; j < 8; j++)
                    acc[i][j] += ra[i] * rb[j];
        }
        __syncthreads();
    }
    #pragma unroll
    for (int i = 0; i < 8; i++) {
        int r = bm + ty*8 + i;
        #pragma unroll
        for (int j = 0; j < 8; j++) {
            int c = bn + tx*8 + j;
            float v = acc[i][j];
            if (mode == 1)      v = v + bias[c];
            else if (mode == 2) v = (v + bias[c]) * scale;
            else if (mode == 3) v = v + bias[c] + res[(size_t)r*N + c];
            C[(size_t)r*N + c] = v;
        }
    }
}

__global__ void k_gemm(const float* __restrict__ A, const float* __restrict__ B,
                       float* __restrict__ C, int M, int N, int K,
                       const float* __restrict__ bias, const float* __restrict__ res,
                       float scale, int mode)
{
    sgemm_tile(A, B, C, M, N, K, bias, res, scale, mode);
}

// ---------------- attention: scores = Q K^T + mask ----------------
// grid: (Sq/64, Skv/64, B*NH); q layout [b,s,h*64+d] (pre-scaled), k layout [b,s,kvh*64+d]
__global__ void k_scores(const float* __restrict__ q, const float* __restrict__ kmat,
                         const float* __restrict__ mask, float* __restrict__ out, int Skv)
{
    int z = blockIdx.z;
    int b = z / NHc, h = z % NHc, kvh = h >> 2;
    int q0 = blockIdx.x * 64, k0 = blockIdx.y * 64;
    __shared__ float Qs[64][65];
    __shared__ float Ks[64][65];
    int tid = threadIdx.x;

    for (int t = tid; t < 1024; t += 256) {      // 64 rows x 16 float4
        int r = t >> 4, c = (t & 15) << 2;
        float4 v = *reinterpret_cast<const float4*>(
            q + (size_t)(b*Sc + q0 + r)*Dc + h*HDc + c);
        Qs[r][c] = v.x; Qs[r][c+1] = v.y; Qs[r][c+2] = v.z; Qs[r][c+3] = v.w;
        float4 w = *reinterpret_cast<const float4*>(
            kmat + (size_t)(b*Skv + k0 + r)*KVDc + kvh*HDc + c);
        Ks[r][c] = w.x; Ks[r][c+1] = w.y; Ks[r][c+2] = w.z; Ks[r][c+3] = w.w;
    }
    __syncthreads();

    int tx = tid & 15, ty = tid >> 4;
    float acc[4][4];
    #pragma unroll
    for (int i = 0; i < 4; i++)
        #pragma unroll
        for (int j = 0; j < 4; j++) acc[i][j] = 0.f;

    #pragma unroll 8
    for (int kk = 0; kk < 64; kk++) {
        float a[4], bb[4];
        #pragma unroll
        for (int i = 0; i < 4; i++) a[i]  = Qs[ty*4 + i][kk];
        #pragma unroll
        for (int j = 0; j < 4; j++) bb[j] = Ks[tx*4 + j][kk];
        #pragma unroll
        for (int i = 0; i < 4; i++)
            #pragma unroll
            for (int j = 0; j < 4; j++) acc[i][j] += a[i] * bb[j];
    }
    #pragma unroll
    for (int i = 0; i < 4; i++) {
        int qr = q0 + ty*4 + i;
        #pragma unroll
        for (int j = 0; j < 4; j++) {
            int kc = k0 + tx*4 + j;
            out[((size_t)z*Sc + qr)*Skv + kc] =
                acc[i][j] + mask[((size_t)b*Sc + qr)*Skv + kc];
        }
    }
}

// ---------------- row softmax (warp per row) ----------------
__global__ void k_softmax(float* __restrict__ s, int L) {
    int row  = blockIdx.x * 8 + (threadIdx.x >> 5);
    int lane = threadIdx.x & 31;
    float* p = s + (size_t)row * L;
    float m = -3.4e38f;
    for (int i = lane; i < L; i += 32) m = fmaxf(m, p[i]);
    #pragma unroll
    for (int off = 16; off > 0; off >>= 1) m = fmaxf(m, __shfl_xor_sync(0xffffffffu, m, off));
    float sum = 0.f;
    for (int i = lane; i < L; i += 32) { float e = __expf(p[i] - m); p[i] = e; sum += e; }
    #pragma unroll
    for (int off = 16; off > 0; off >>= 1) sum += __shfl_xor_sync(0xffffffffu, sum, off);
    float inv = 1.f / sum;
    for (int i = lane; i < L; i += 32) p[i] *= inv;
}

// ---------------- attention: ctx = P V ----------------
// grid: (Sq/64, 1, B*NH); writes ctx[b,s,h*64+d]
__global__ void k_pv(const float* __restrict__ sm, const float* __restrict__ v,
                     float* __restrict__ ctx, int Skv)
{
    int z = blockIdx.z;
    int b = z / NHc, h = z % NHc, kvh = h >> 2;
    int q0 = blockIdx.x * 64;
    __shared__ float Ps[64][65];
    __shared__ float Vs[64][65];
    int tid = threadIdx.x;
    int tx = tid & 15, ty = tid >> 4;

    float acc[4][4];
    #pragma unroll
    for (int i = 0; i < 4; i++)
        #pragma unroll
        for (int j = 0; j < 4; j++) acc[i][j] = 0.f;

    for (int kc = 0; kc < Skv; kc += 64) {
        for (int t = tid; t < 1024; t += 256) {
            int r = t >> 4, c = (t & 15) << 2;
            float4 pv = *reinterpret_cast<const float4*>(
                sm + ((size_t)z*Sc + q0 + r)*Skv + kc + c);
            Ps[r][c] = pv.x; Ps[r][c+1] = pv.y; Ps[r][c+2] = pv.z; Ps[r][c+3] = pv.w;
            float4 vv = *reinterpret_cast<const float4*>(
                v + (size_t)(b*Skv + kc + r)*KVDc + kvh*HDc + c);
            Vs[r][c] = vv.x; Vs[r][c+1] = vv.y; Vs[r][c+2] = vv.z; Vs[r][c+3] = vv.w;
        }
        __syncthreads();
        #pragma unroll 8
        for (int kk = 0; kk < 64; kk++) {
            float a[4], bb[4];
            #pragma unroll
            for (int i = 0; i < 4; i++) a[i]  = Ps[ty*4 + i][kk];
            #pragma unroll
            for (int j = 0; j < 4; j++) bb[j] = Vs[kk][tx*4 + j];
            #pragma unroll
            for (int i = 0; i < 4; i++)
                #pragma unroll
                for (int j = 0; j < 4; j++) acc[i][j] += a[i] * bb[j];
        }
        __syncthreads();
    }
    #pragma unroll
    for (int i = 0; i < 4; i++) {
        int qr = q0 + ty*4 + i;
        #pragma unroll
        for (int j = 0; j < 4; j++)
            ctx[(size_t)(b*Sc + qr)*Dc + h*HDc + tx*4 + j] = acc[i][j];
    }
}

// ---------------- MoE GEMMs (early-exit on coef==0) ----------------
__global__ void k_moe_up(const float* __restrict__ x, const float* __restrict__ W,
                         float* __restrict__ out)
{
    int p = blockIdx.z;
    if (g_coef[p] == 0.f) return;
    int e = p / Bc, b = p % Bc;
    sgemm_tile(x + (size_t)b*Sc*Dc, W + (size_t)e*Dc*DEc, out + (size_t)p*Sc*DEc,
               Sc, DEc, Dc, nullptr, nullptr, 1.f, 0);
}

__global__ void k_moe_down(const float* __restrict__ h, const float* __restrict__ W,
                           float* __restrict__ out)
{
    int p = blockIdx.z;
    if (g_coef[p] == 0.f) return;
    int e = p / Bc;
    sgemm_tile(h + (size_t)p*Sc*DEc, W + (size_t)e*DEc*Dc, out + (size_t)p*Sc*Dc,
               Sc, Dc, DEc, nullptr, nullptr, 1.f, 0);
}

__device__ __forceinline__ float gelu_exact(float x) {
    return 0.5f * x * (1.f + erff(x * 0.70710678118654752f));
}

// h = gelu(t1) * t3, stored back into t1. grid: (S*DE/1024, E*B)
__global__ void k_moe_act(float* __restrict__ t1, const float* __restrict__ t3) {
    int p = blockIdx.y;
    if (g_coef[p] == 0.f) return;
    size_t base = (size_t)p*Sc*DEc + ((size_t)blockIdx.x*256 + threadIdx.x)*4;
    float4 a = *reinterpret_cast<float4*>(t1 + base);
    float4 c = *reinterpret_cast<const float4*>(t3 + base);
    a.x = gelu_exact(a.x) * c.x;
    a.y = gelu_exact(a.y) * c.y;
    a.z = gelu_exact(a.z) * c.z;
    a.w = gelu_exact(a.w) * c.w;
    *reinterpret_cast<float4*>(t1 + base) = a;
}

// out = res + sum_e coef[e,b] * pout[e,b]
__global__ void k_final(const float* __restrict__ res, const float* __restrict__ pout,
                        float* __restrict__ out)
{
    int idx = blockIdx.x * 256 + threadIdx.x;
    int b   = idx / (Sc*Dc);
    int off = idx - b*(Sc*Dc);
    float v = res[idx];
    #pragma unroll
    for (int e = 0; e < NEc; e++) {
        float cf = g_coef[e*Bc + b];
        if (cf != 0.f) v += cf * pout[(size_t)(e*Bc + b)*Sc*Dc + off];
    }
    out[idx] = v;
}

// ---------------- launch ----------------
extern "C" void kernel_launch(void* const* d_in, const int* in_sizes, int n_in,
                              void* d_out, int out_size)
{
    (void)in_sizes; (void)n_in; (void)out_size;
    const float* hid   = (const float*)d_in[0];
    const float* enc   = (const float*)d_in[1];
    const float* amask = (const float*)d_in[2];
    const float* emask = (const float*)d_in[3];
    const int*   langs = (const int*)  d_in[4];
    const float* ln1g  = (const float*)d_in[5];
    const float* ln1b  = (const float*)d_in[6];
    const float* saqw  = (const float*)d_in[7];
    const float* saqb  = (const float*)d_in[8];
    const float* sakw  = (const float*)d_in[9];
    const float* sakb  = (const float*)d_in[10];
    const float* savw  = (const float*)d_in[11];
    const float* savb  = (const float*)d_in[12];
    const float* saow  = (const float*)d_in[13];
    const float* saob  = (const float*)d_in[14];
    const float* ln2g  = (const float*)d_in[15];
    const float* ln2b  = (const float*)d_in[16];
    const float* caqw  = (const float*)d_in[17];
    const float* caqb  = (const float*)d_in[18];
    const float* cakw  = (const float*)d_in[19];
    const float* cakb  = (const float*)d_in[20];
    const float* cavw  = (const float*)d_in[21];
    const float* cavb  = (const float*)d_in[22];
    const float* caow  = (const float*)d_in[23];
    const float* caob  = (const float*)d_in[24];
    const float* ln3g  = (const float*)d_in[25];
    const float* ln3b  = (const float*)d_in[26];
    const float* w1    = (const float*)d_in[27];
    const float* w2    = (const float*)d_in[28];
    const float* w3    = (const float*)d_in[29];
    float* out = (float*)d_out;

    float *p_ln, *p_q, *p_k, *p_v, *p_s, *p_ctx, *p_res, *p_t1, *p_t3, *p_pout;
    cudaGetSymbolAddress((void**)&p_ln,   g_ln);
    cudaGetSymbolAddress((void**)&p_q,    g_q);
    cudaGetSymbolAddress((void**)&p_k,    g_k);
    cudaGetSymbolAddress((void**)&p_v,    g_v);
    cudaGetSymbolAddress((void**)&p_s,    g_sc);
    cudaGetSymbolAddress((void**)&p_ctx,  g_ctx);
    cudaGetSymbolAddress((void**)&p_res,  g_res);
    cudaGetSymbolAddress((void**)&p_t1,   g_t1);
    cudaGetSymbolAddress((void**)&p_t3,   g_t3);
    cudaGetSymbolAddress((void**)&p_pout, g_pout);

    const int M = Bc*Sc;       // 1024
    const int ME = Bc*SKc;     // 2048

    k_route<<<1, 32>>>(langs);

    // ===== self attention (causal GQA) =====
    k_ln<<<M, 256>>>(hid, ln1g, ln1b, p_ln);
    k_gemm<<<dim3(Dc/128,   M/128), 256>>>(p_ln, saqw, p_q, M, Dc,   Dc, saqb, nullptr, QSCALE, 2);
    k_gemm<<<dim3(KVDc/128, M/128), 256>>>(p_ln, sakw, p_k, M, KVDc, Dc, sakb, nullptr, 1.f, 1);
    k_gemm<<<dim3(KVDc/128, M/128), 256>>>(p_ln, savw, p_v, M, KVDc, Dc, savb, nullptr, 1.f, 1);
    k_scores<<<dim3(Sc/64, Sc/64, Bc*NHc), 256>>>(p_q, p_k, amask, p_s, Sc);
    k_softmax<<<(Bc*NHc*Sc)/8, 256>>>(p_s, Sc);
    k_pv<<<dim3(Sc/64, 1, Bc*NHc), 256>>>(p_s, p_v, p_ctx, Sc);
    k_gemm<<<dim3(Dc/128, M/128), 256>>>(p_ctx, saow, p_res, M, Dc, Dc, saob, hid, 1.f, 3);

    // ===== cross attention over encoder states =====
    k_ln<<<M, 256>>>(p_res, ln2g, ln2b, p_ln);
    k_gemm<<<dim3(Dc/128,   M/128),  256>>>(p_ln, caqw, p_q, M,  Dc,   Dc, caqb, nullptr, QSCALE, 2);
    k_gemm<<<dim3(KVDc/128, ME/128), 256>>>(enc,  cakw, p_k, ME, KVDc, Dc, cakb, nullptr, 1.f, 1);
    k_gemm<<<dim3(KVDc/128, ME/128), 256>>>(enc,  cavw, p_v, ME, KVDc, Dc, cavb, nullptr, 1.f, 1);
    k_scores<<<dim3(Sc/64, SKc/64, Bc*NHc), 256>>>(p_q, p_k, emask, p_s, SKc);
    k_softmax<<<(Bc*NHc*Sc)/8, 256>>>(p_s, SKc);
    k_pv<<<dim3(Sc/64, 1, Bc*NHc), 256>>>(p_s, p_v, p_ctx, SKc);
    k_gemm<<<dim3(Dc/128, M/128), 256>>>(p_ctx, caow, p_res, M, Dc, Dc, caob, p_res, 1.f, 3);

    // ===== language-routed MoE FFN =====
    k_ln<<<M, 256>>>(p_res, ln3g, ln3b, p_ln);
    k_moe_up<<<dim3(DEc/128, Sc/128, NEc*Bc), 256>>>(p_ln, w1, p_t1);
    k_moe_up<<<dim3(DEc/128, Sc/128, NEc*Bc), 256>>>(p_ln, w3, p_t3);
    k_moe_act<<<dim3((Sc*DEc)/1024, NEc*Bc), 256>>>(p_t1, p_t3);
    k_moe_down<<<dim3(Dc/128, Sc/128, NEc*Bc), 256>>>(p_t1, w2, p_pout);
    k_final<<<(Bc*Sc*Dc)/256, 256>>>(p_res, p_pout, out);
}

// round 5
// speedup vs baseline: 1.0023x; 1.0023x over previous
#include <cuda_runtime.h>
#include <cuda_bf16.h>
#include <math.h>

// ---------------- problem constants ----------------
#define Bc   4
#define Sc   256
#define SKc  512
#define Dc   1024
#define NHc  16
#define NKVc 4
#define HDc  64
#define KVDc (NKVc*HDc)   // 256
#define DEc  4096
#define NEc  8
#define LN_EPS 1e-5f
#define QSCALE 0.125f     // HD^-0.5

// ---------------- scratch (device globals; no allocs allowed) ----------------
__device__ float g_ln  [Bc*Sc*Dc];                       // 4 MB  (reused for ln1/ln2/ln3)
__device__ float g_q   [Bc*Sc*Dc];                       // 4 MB
__device__ float g_k   [Bc*SKc*KVDc];                    // 2 MB  (self uses first B*S rows)
__device__ float g_v   [Bc*SKc*KVDc];                    // 2 MB
__device__ float g_sc  [(size_t)Bc*NHc*Sc*SKc];          // 32 MB (scores, max Skv=512)
__device__ float g_ctx [Bc*Sc*Dc];                       // 4 MB
__device__ float g_res [Bc*Sc*Dc];                       // 4 MB  (running hidden)
__device__ float g_t1  [(size_t)NEc*Bc*Sc*DEc];          // 128 MB (x@w1, then h)
__device__ float g_t3  [(size_t)NEc*Bc*Sc*DEc];          // 128 MB (x@w3)
__device__ float g_pout[(size_t)NEc*Bc*Sc*Dc];           // 32 MB (per-pair expert out)
__device__ float g_coef[NEc*Bc];

// ---------------- routing ----------------
__global__ void k_route(const int* __restrict__ langs) {
    if (threadIdx.x == 0 && blockIdx.x == 0) {
        for (int b = 0; b < Bc; b++) {
            int l0 = langs[2*b], l1 = langs[2*b+1];
            int cnt = (l0 > 3) + (l1 > 3);
            float rw = (cnt == 0) ? 1.f : 1.f / (float)cnt;
            for (int e = 0; e < NEc; e++) {
                int code = 4 + e;
                g_coef[e*Bc + b] = ((l0 == code) || (l1 == code)) ? rw : 0.f;
            }
        }
    }
}

// ---------------- layernorm (block per row) ----------------
__global__ void k_ln(const float* __restrict__ x, const float* __restrict__ g,
                     const float* __restrict__ bta, float* __restrict__ y) {
    int row = blockIdx.x;
    int tid = threadIdx.x;
    const float* xr = x + (size_t)row * Dc;
    float s = 0.f, s2 = 0.f;
    for (int i = tid; i < Dc; i += 256) { float v = xr[i]; s += v; s2 += v*v; }
    __shared__ float r1[256], r2[256];
    r1[tid] = s; r2[tid] = s2; __syncthreads();
    for (int off = 128; off > 0; off >>= 1) {
        if (tid < off) { r1[tid] += r1[tid+off]; r2[tid] += r2[tid+off]; }
        __syncthreads();
    }
    float mean = r1[0] * (1.f/Dc);
    float var  = r2[0] * (1.f/Dc) - mean*mean;
    float inv  = rsqrtf(var + LN_EPS);
    for (int i = tid; i < Dc; i += 256)
        y[(size_t)row*Dc + i] = (xr[i] - mean) * inv * g[i] + bta[i];
}

// ---------------- generic 128x128x8 SGEMM body ----------------
// mode: 0 = plain, 1 = +bias, 2 = (+bias)*scale, 3 = +bias+res
__device__ __forceinline__ void sgemm_tile(
    const float* __restrict__ A, const float* __restrict__ Bm, float* __restrict__ C,
    int M, int N, int K,
    const float* __restrict__ bias, const float* __restrict__ res,
    float scale, int mode)
{
    __shared__ float As[8][128];
    __shared__ float Bs[8][128];
    int tid = threadIdx.x;
    int bm = blockIdx.y * 128;
    int bn = blockIdx.x * 128;
    int tx = tid & 15, ty = tid >> 4;

    float acc[8][8];
    #pragma unroll
    for (int i = 0; i < 8; i++)
        #pragma unroll
        for (int j = 0; j < 8; j++) acc[i][j] = 0.f;

    int aRow = tid >> 1;             // 0..127
    int aCol = (tid & 1) * 4;        // 0 or 4
    int bRow = tid >> 5;             // 0..7
    int bCol = (tid & 31) * 4;       // 0..124

    const float* Ag = A  + (size_t)(bm + aRow) * K + aCol;
    const float* Bg = Bm + (size_t)bRow * N + bn + bCol;

    for (int k0 = 0; k0 < K; k0 += 8) {
        float4 a4 = *reinterpret_cast<const float4*>(Ag + k0);
        As[aCol+0][aRow] = a4.x;
        As[aCol+1][aRow] = a4.y;
        As[aCol+2][aRow] = a4.z;
        As[aCol+3][aRow] = a4.w;
        float4 b4 = *reinterpret_cast<const float4*>(Bg + (size_t)k0 * N);
        *reinterpret_cast<float4*>(&Bs[bRow][bCol]) = b4;
        __syncthreads();
        #pragma unroll
        for (int kk = 0; kk < 8; kk++) {
            float ra[8], rb[8];
            #pragma unroll
            for (int i = 0; i < 8; i++) ra[i] = As[kk][ty*8 + i];
            #pragma unroll
            for (int j = 0; j < 8; j++) rb[j] = Bs[kk][tx*8 + j];
            #pragma unroll
            for (int i = 0; i < 8; i++)
                #pragma unroll
                for (int j = 0; j < 8; j++)
                    acc[i][j] += ra[i] * rb[j];
        }
        __syncthreads();
    }
    #pragma unroll
    for (int i = 0; i < 8; i++) {
        int r = bm + ty*8 + i;
        #pragma unroll
        for (int j = 0; j < 8; j++) {
            int c = bn + tx*8 + j;
            float v = acc[i][j];
            if (mode == 1)      v = v + bias[c];
            else if (mode == 2) v = (v + bias[c]) * scale;
            else if (mode == 3) v = v + bias[c] + res[(size_t)r*N + c];
            C[(size_t)r*N + c] = v;
        }
    }
}

__global__ void k_gemm(const float* __restrict__ A, const float* __restrict__ B,
                       float* __restrict__ C, int M, int N, int K,
                       const float* __restrict__ bias, const float* __restrict__ res,
                       float scale, int mode)
{
    sgemm_tile(A, B, C, M, N, K, bias, res, scale, mode);
}

// ---------------- attention: scores = Q K^T + mask ----------------
// grid: (Sq/64, Skv/64, B*NH); q layout [b,s,h*64+d] (pre-scaled), k layout [b,s,kvh*64+d]
__global__ void k_scores(const float* __restrict__ q, const float* __restrict__ kmat,
                         const float* __restrict__ mask, float* __restrict__ out, int Skv)
{
    int z = blockIdx.z;
    int b = z / NHc, h = z % NHc, kvh = h >> 2;
    int q0 = blockIdx.x * 64, k0 = blockIdx.y * 64;
    __shared__ float Qs[64][65];
    __shared__ float Ks[64][65];
    int tid = threadIdx.x;

    for (int t = tid; t < 1024; t += 256) {      // 64 rows x 16 float4
        int r = t >> 4, c = (t & 15) << 2;
        float4 v = *reinterpret_cast<const float4*>(
            q + (size_t)(b*Sc + q0 + r)*Dc + h*HDc + c);
        Qs[r][c] = v.x; Qs[r][c+1] = v.y; Qs[r][c+2] = v.z; Qs[r][c+3] = v.w;
        float4 w = *reinterpret_cast<const float4*>(
            kmat + (size_t)(b*Skv + k0 + r)*KVDc + kvh*HDc + c);
        Ks[r][c] = w.x; Ks[r][c+1] = w.y; Ks[r][c+2] = w.z; Ks[r][c+3] = w.w;
    }
    __syncthreads();

    int tx = tid & 15, ty = tid >> 4;
    float acc[4][4];
    #pragma unroll
    for (int i = 0; i < 4; i++)
        #pragma unroll
        for (int j = 0; j < 4; j++) acc[i][j] = 0.f;

    #pragma unroll 8
    for (int kk = 0; kk < 64; kk++) {
        float a[4], bb[4];
        #pragma unroll
        for (int i = 0; i < 4; i++) a[i]  = Qs[ty*4 + i][kk];
        #pragma unroll
        for (int j = 0; j < 4; j++) bb[j] = Ks[tx*4 + j][kk];
        #pragma unroll
        for (int i = 0; i < 4; i++)
            #pragma unroll
            for (int j = 0; j < 4; j++) acc[i][j] += a[i] * bb[j];
    }
    #pragma unroll
    for (int i = 0; i < 4; i++) {
        int qr = q0 + ty*4 + i;
        #pragma unroll
        for (int j = 0; j < 4; j++) {
            int kc = k0 + tx*4 + j;
            out[((size_t)z*Sc + qr)*Skv + kc] =
                acc[i][j] + mask[((size_t)b*Sc + qr)*Skv + kc];
        }
    }
}

// ---------------- row softmax (warp per row) ----------------
__global__ void k_softmax(float* __restrict__ s, int L) {
    int row  = blockIdx.x * 8 + (threadIdx.x >> 5);
    int lane = threadIdx.x & 31;
    float* p = s + (size_t)row * L;
    float m = -3.4e38f;
    for (int i = lane; i < L; i += 32) m = fmaxf(m, p[i]);
    #pragma unroll
    for (int off = 16; off > 0; off >>= 1) m = fmaxf(m, __shfl_xor_sync(0xffffffffu, m, off));
    float sum = 0.f;
    for (int i = lane; i < L; i += 32) { float e = __expf(p[i] - m); p[i] = e; sum += e; }
    #pragma unroll
    for (int off = 16; off > 0; off >>= 1) sum += __shfl_xor_sync(0xffffffffu, sum, off);
    float inv = 1.f / sum;
    for (int i = lane; i < L; i += 32) p[i] *= inv;
}

// ---------------- attention: ctx = P V ----------------
// grid: (Sq/64, 1, B*NH); writes ctx[b,s,h*64+d]
__global__ void k_pv(const float* __restrict__ sm, const float* __restrict__ v,
                     float* __restrict__ ctx, int Skv)
{
    int z = blockIdx.z;
    int b = z / NHc, h = z % NHc, kvh = h >> 2;
    int q0 = blockIdx.x * 64;
    __shared__ float Ps[64][65];
    __shared__ float Vs[64][65];
    int tid = threadIdx.x;
    int tx = tid & 15, ty = tid >> 4;

    float acc[4][4];
    #pragma unroll
    for (int i = 0; i < 4; i++)
        #pragma unroll
        for (int j = 0; j < 4; j++) acc[i][j] = 0.f;

    for (int kc = 0; kc < Skv; kc += 64) {
        for (int t = tid; t < 1024; t += 256) {
            int r = t >> 4, c = (t & 15) << 2;
            float4 pv = *reinterpret_cast<const float4*>(
                sm + ((size_t)z*Sc + q0 + r)*Skv + kc + c);
            Ps[r][c] = pv.x; Ps[r][c+1] = pv.y; Ps[r][c+2] = pv.z; Ps[r][c+3] = pv.w;
            float4 vv = *reinterpret_cast<const float4*>(
                v + (size_t)(b*Skv + kc + r)*KVDc + kvh*HDc + c);
            Vs[r][c] = vv.x; Vs[r][c+1] = vv.y; Vs[r][c+2] = vv.z; Vs[r][c+3] = vv.w;
        }
        __syncthreads();
        #pragma unroll 8
        for (int kk = 0; kk < 64; kk++) {
            float a[4], bb[4];
            #pragma unroll
            for (int i = 0; i < 4; i++) a[i]  = Ps[ty*4 + i][kk];
            #pragma unroll
            for (int j = 0; j < 4; j++) bb[j] = Vs[kk][tx*4 + j];
            #pragma unroll
            for (int i = 0; i < 4; i++)
                #pragma unroll
                for (int j = 0; j < 4; j++) acc[i][j] += a[i] * bb[j];
        }
        __syncthreads();
    }
    #pragma unroll
    for (int i = 0; i < 4; i++) {
        int qr = q0 + ty*4 + i;
        #pragma unroll
        for (int j = 0; j < 4; j++)
            ctx[(size_t)(b*Sc + qr)*Dc + h*HDc + tx*4 + j] = acc[i][j];
    }
}

// ---------------- MoE GEMMs (early-exit on coef==0) ----------------
__global__ void k_moe_up(const float* __restrict__ x, const float* __restrict__ W,
                         float* __restrict__ out)
{
    int p = blockIdx.z;
    if (g_coef[p] == 0.f) return;
    int e = p / Bc, b = p % Bc;
    sgemm_tile(x + (size_t)b*Sc*Dc, W + (size_t)e*Dc*DEc, out + (size_t)p*Sc*DEc,
               Sc, DEc, Dc, nullptr, nullptr, 1.f, 0);
}

__global__ void k_moe_down(const float* __restrict__ h, const float* __restrict__ W,
                           float* __restrict__ out)
{
    int p = blockIdx.z;
    if (g_coef[p] == 0.f) return;
    int e = p / Bc;
    sgemm_tile(h + (size_t)p*Sc*DEc, W + (size_t)e*DEc*Dc, out + (size_t)p*Sc*Dc,
               Sc, Dc, DEc, nullptr, nullptr, 1.f, 0);
}

__device__ __forceinline__ float gelu_exact(float x) {
    return 0.5f * x * (1.f + erff(x * 0.70710678118654752f));
}

// h = gelu(t1) * t3, stored back into t1. grid: (S*DE/1024, E*B)
__global__ void k_moe_act(float* __restrict__ t1, const float* __restrict__ t3) {
    int p = blockIdx.y;
    if (g_coef[p] == 0.f) return;
    size_t base = (size_t)p*Sc*DEc + ((size_t)blockIdx.x*256 + threadIdx.x)*4;
    float4 a = *reinterpret_cast<float4*>(t1 + base);
    float4 c = *reinterpret_cast<const float4*>(t3 + base);
    a.x = gelu_exact(a.x) * c.x;
    a.y = gelu_exact(a.y) * c.y;
    a.z = gelu_exact(a.z) * c.z;
    a.w = gelu_exact(a.w) * c.w;
    *reinterpret_cast<float4*>(t1 + base) = a;
}

// out = res + sum_e coef[e,b] * pout[e,b]
__global__ void k_final(const float* __restrict__ res, const float* __restrict__ pout,
                        float* __restrict__ out)
{
    int idx = blockIdx.x * 256 + threadIdx.x;
    int b   = idx / (Sc*Dc);
    int off = idx - b*(Sc*Dc);
    float v = res[idx];
    #pragma unroll
    for (int e = 0; e < NEc; e++) {
        float cf = g_coef[e*Bc + b];
        if (cf != 0.f) v += cf * pout[(size_t)(e*Bc + b)*Sc*Dc + off];
    }
    out[idx] = v;
}

// ---------------- launch ----------------
extern "C" void kernel_launch(void* const* d_in, const int* in_sizes, int n_in,
                              void* d_out, int out_size)
{
    (void)in_sizes; (void)n_in; (void)out_size;
    const float* hid   = (const float*)d_in[0];
    const float* enc   = (const float*)d_in[1];
    const float* amask = (const float*)d_in[2];
    const float* emask = (const float*)d_in[3];
    const int*   langs = (const int*)  d_in[4];
    const float* ln1g  = (const float*)d_in[5];
    const float* ln1b  = (const float*)d_in[6];
    const float* saqw  = (const float*)d_in[7];
    const float* saqb  = (const float*)d_in[8];
    const float* sakw  = (const float*)d_in[9];
    const float* sakb  = (const float*)d_in[10];
    const float* savw  = (const float*)d_in[11];
    const float* savb  = (const float*)d_in[12];
    const float* saow  = (const float*)d_in[13];
    const float* saob  = (const float*)d_in[14];
    const float* ln2g  = (const float*)d_in[15];
    const float* ln2b  = (const float*)d_in[16];
    const float* caqw  = (const float*)d_in[17];
    const float* caqb  = (const float*)d_in[18];
    const float* cakw  = (const float*)d_in[19];
    const float* cakb  = (const float*)d_in[20];
    const float* cavw  = (const float*)d_in[21];
    const float* cavb  = (const float*)d_in[22];
    const float* caow  = (const float*)d_in[23];
    const float* caob  = (const float*)d_in[24];
    const float* ln3g  = (const float*)d_in[25];
    const float* ln3b  = (const float*)d_in[26];
    const float* w1    = (const float*)d_in[27];
    const float* w2    = (const float*)d_in[28];
    const float* w3    = (const float*)d_in[29];
    float* out = (float*)d_out;

    float *p_ln, *p_q, *p_k, *p_v, *p_s, *p_ctx, *p_res, *p_t1, *p_t3, *p_pout;
    cudaGetSymbolAddress((void**)&p_ln,   g_ln);
    cudaGetSymbolAddress((void**)&p_q,    g_q);
    cudaGetSymbolAddress((void**)&p_k,    g_k);
    cudaGetSymbolAddress((void**)&p_v,    g_v);
    cudaGetSymbolAddress((void**)&p_s,    g_sc);
    cudaGetSymbolAddress((void**)&p_ctx,  g_ctx);
    cudaGetSymbolAddress((void**)&p_res,  g_res);
    cudaGetSymbolAddress((void**)&p_t1,   g_t1);
    cudaGetSymbolAddress((void**)&p_t3,   g_t3);
    cudaGetSymbolAddress((void**)&p_pout, g_pout);

    const int M = Bc*Sc;       // 1024
    const int ME = Bc*SKc;     // 2048

    k_route<<<1, 32>>>(langs);

    // ===== self attention (causal GQA) =====
    k_ln<<<M, 256>>>(hid, ln1g, ln1b, p_ln);
    k_gemm<<<dim3(Dc/128,   M/128), 256>>>(p_ln, saqw, p_q, M, Dc,   Dc, saqb, nullptr, QSCALE, 2);
    k_gemm<<<dim3(KVDc/128, M/128), 256>>>(p_ln, sakw, p_k, M, KVDc, Dc, sakb, nullptr, 1.f, 1);
    k_gemm<<<dim3(KVDc/128, M/128), 256>>>(p_ln, savw, p_v, M, KVDc, Dc, savb, nullptr, 1.f, 1);
    k_scores<<<dim3(Sc/64, Sc/64, Bc*NHc), 256>>>(p_q, p_k, amask, p_s, Sc);
    k_softmax<<<(Bc*NHc*Sc)/8, 256>>>(p_s, Sc);
    k_pv<<<dim3(Sc/64, 1, Bc*NHc), 256>>>(p_s, p_v, p_ctx, Sc);
    k_gemm<<<dim3(Dc/128, M/128), 256>>>(p_ctx, saow, p_res, M, Dc, Dc, saob, hid, 1.f, 3);

    // ===== cross attention over encoder states =====
    k_ln<<<M, 256>>>(p_res, ln2g, ln2b, p_ln);
    k_gemm<<<dim3(Dc/128,   M/128),  256>>>(p_ln, caqw, p_q, M,  Dc,   Dc, caqb, nullptr, QSCALE, 2);
    k_gemm<<<dim3(KVDc/128, ME/128), 256>>>(enc,  cakw, p_k, ME, KVDc, Dc, cakb, nullptr, 1.f, 1);
    k_gemm<<<dim3(KVDc/128, ME/128), 256>>>(enc,  cavw, p_v, ME, KVDc, Dc, cavb, nullptr, 1.f, 1);
    k_scores<<<dim3(Sc/64, SKc/64, Bc*NHc), 256>>>(p_q, p_k, emask, p_s, SKc);
    k_softmax<<<(Bc*NHc*Sc)/8, 256>>>(p_s, SKc);
    k_pv<<<dim3(Sc/64, 1, Bc*NHc), 256>>>(p_s, p_v, p_ctx, SKc);
    k_gemm<<<dim3(Dc/128, M/128), 256>>>(p_ctx, caow, p_res, M, Dc, Dc, caob, p_res, 1.f, 3);

    // ===== language-routed MoE FFN =====
    k_ln<<<M, 256>>>(p_res, ln3g, ln3b, p_ln);
    k_moe_up<<<dim3(DEc/128, Sc/128, NEc*Bc), 256>>>(p_ln, w1, p_t1);
    k_moe_up<<<dim3(DEc/128, Sc/128, NEc*Bc), 256>>>(p_ln, w3, p_t3);
    k_moe_act<<<dim3((Sc*DEc)/1024, NEc*Bc), 256>>>(p_t1, p_t3);
    k_moe_down<<<dim3(Dc/128, Sc/128, NEc*Bc), 256>>>(p_t1, w2, p_pout);
    k_final<<<(Bc*Sc*Dc)/256, 256>>>(p_res, p_pout, out);
}